// round 4
// baseline (speedup 1.0000x reference)
#include <cuda_runtime.h>
#include <cstdint>

#define NN 16384
#define MM 8192
#define EE 524288
#define DD 128

// ---------------- GEMM tiling ----------------
#define BM 128
#define BN 128
#define BK 32
#define AST 36      // A smem pitch (floats): 144B, 16B aligned, conflict-free frags
#define BST 132     // B smem pitch (floats): 528B, 16B aligned, conflict-free frags
#define SMEM_FLOATS (2*BM*AST + 2*BK*BST)   // 17664 floats
#define SMEM_BYTES  (SMEM_FLOATS*4)         // 70656 B (also covers 128x133 LN buffer)
#define EPI_PITCH 133

// ---------------- device scratch (static, no allocation) ----------------
__device__ int   g_out_cnt[NN];
__device__ int   g_in_cnt[NN];
__device__ int   g_cursor[NN];
__device__ int   g_row_ptr[NN+1];
__device__ int   g_csr[EE];
__device__ float g_rs_out[NN];
__device__ float g_rs_in[NN];
__device__ float g_xc[NN*DD];        // curr_h * rsqrt(out_deg)
__device__ float g_xf[NN*DD];        // (inc @ nh) * rsqrt(out_deg)
__device__ float g_agg[NN*2*DD];     // [aggc | aggf] per row
__device__ float g_nh_t[MM*DD];      // tf32-rounded next_h
__device__ float g_wcat[2*DD*DD];    // [Wc*cw ; Wf*tw] * 0.5, tf32-rounded
__device__ float g_b2[DD];

// ---------------- helpers ----------------
__device__ __forceinline__ uint32_t f2tf(float x){
    uint32_t r; asm("cvt.rna.tf32.f32 %0, %1;" : "=r"(r) : "f"(x)); return r;
}
__device__ __forceinline__ void cp16(float* s, const float* g){
    unsigned sa = (unsigned)__cvta_generic_to_shared(s);
    asm volatile("cp.async.cg.shared.global [%0], [%1], 16;\n" :: "r"(sa), "l"(g));
}
__device__ __forceinline__ void mma8(float* c, const uint32_t* a, uint32_t b0, uint32_t b1){
    asm volatile("mma.sync.aligned.m16n8k8.row.col.f32.tf32.tf32.f32 "
        "{%0,%1,%2,%3},{%4,%5,%6,%7},{%8,%9},{%0,%1,%2,%3};\n"
        : "+f"(c[0]),"+f"(c[1]),"+f"(c[2]),"+f"(c[3])
        : "r"(a[0]),"r"(a[1]),"r"(a[2]),"r"(a[3]),"r"(b0),"r"(b1));
}

// ---------------- small kernels ----------------
__global__ void zero_kernel(){
    int i = blockIdx.x*blockDim.x + threadIdx.x;
    if (i < NN){ g_out_cnt[i]=0; g_in_cnt[i]=0; g_cursor[i]=0; }
}

__global__ void degree_kernel(const int* __restrict__ src, const int* __restrict__ dst){
    int e = blockIdx.x*blockDim.x + threadIdx.x;
    if (e < EE){ atomicAdd(&g_out_cnt[src[e]],1); atomicAdd(&g_in_cnt[dst[e]],1); }
}

__global__ void scan_kernel(){   // 1 block, 1024 threads: exclusive scan of in_cnt
    __shared__ int ssum[1024];
    int tid = threadIdx.x;
    int loc[16]; int sum = 0;
    #pragma unroll
    for (int j=0;j<16;j++){ loc[j] = g_in_cnt[tid*16+j]; sum += loc[j]; }
    ssum[tid] = sum; __syncthreads();
    for (int off=1; off<1024; off<<=1){
        int v = (tid >= off) ? ssum[tid-off] : 0;
        __syncthreads();
        ssum[tid] += v;
        __syncthreads();
    }
    int run = ssum[tid] - sum;
    #pragma unroll
    for (int j=0;j<16;j++){ g_row_ptr[tid*16+j] = run; run += loc[j]; }
    if (tid == 1023) g_row_ptr[NN] = run;
    for (int i=tid; i<NN; i+=1024){
        g_rs_in[i]  = rsqrtf((float)g_in_cnt[i]  + 1.f);
        g_rs_out[i] = rsqrtf((float)g_out_cnt[i] + 1.f);
    }
}

__global__ void scatter_kernel(const int* __restrict__ src, const int* __restrict__ dst){
    int e = blockIdx.x*blockDim.x + threadIdx.x;
    if (e < EE){
        int d = dst[e];
        int p = g_row_ptr[d] + atomicAdd(&g_cursor[d], 1);
        g_csr[p] = src[e];
    }
}

__global__ void xc_kernel(const float* __restrict__ curr_h){
    int i = blockIdx.x*blockDim.x + threadIdx.x;   // float4 index
    if (i < NN*DD/4){
        float4 v = ((const float4*)curr_h)[i];
        float s = g_rs_out[i>>5];
        v.x*=s; v.y*=s; v.z*=s; v.w*=s;
        ((float4*)g_xc)[i] = v;
    }
}

__global__ void roundb_kernel(const float* __restrict__ nh){
    int i = blockIdx.x*blockDim.x + threadIdx.x;
    if (i < MM*DD) g_nh_t[i] = __uint_as_float(f2tf(nh[i]));
}

__global__ void prep_kernel(const float* __restrict__ Wc, const float* __restrict__ bc,
                            const float* __restrict__ Wf, const float* __restrict__ bf,
                            const float* __restrict__ cw, const float* __restrict__ tw){
    int i = blockIdx.x*blockDim.x + threadIdx.x;
    if (i < 2*DD*DD){
        int k = i >> 7, j = i & 127;
        float w = (k < DD) ? Wc[k*DD+j]*cw[j] : Wf[(k-DD)*DD+j]*tw[j];
        g_wcat[i] = __uint_as_float(f2tf(0.5f*w));
        if (i < DD) g_b2[i] = 0.5f*(bc[i]*cw[i] + bf[i]*tw[i]);
    }
}

// ---------------- SpMM: warp per destination node, CSR gather ----------------
__global__ void spmm_kernel(){
    int w = (blockIdx.x*blockDim.x + threadIdx.x) >> 5;
    int lane = threadIdx.x & 31;
    if (w >= NN) return;
    const float4* xc4 = (const float4*)g_xc;
    const float4* xf4 = (const float4*)g_xf;
    float4 ac = xc4[w*32 + lane];   // self-loop term
    float4 af = xf4[w*32 + lane];
    int s0 = g_row_ptr[w], s1 = g_row_ptr[w+1];
    int base = s0;
    for (; base + 32 <= s1; base += 32){
        int sv = g_csr[base + lane];
        #pragma unroll 8
        for (int j=0;j<32;j++){
            int s = __shfl_sync(0xffffffffu, sv, j);
            float4 vc = xc4[s*32+lane], vf = xf4[s*32+lane];
            ac.x+=vc.x; ac.y+=vc.y; ac.z+=vc.z; ac.w+=vc.w;
            af.x+=vf.x; af.y+=vf.y; af.z+=vf.z; af.w+=vf.w;
        }
    }
    int rem = s1 - base;
    if (rem > 0){
        int sv = (lane < rem) ? g_csr[base + lane] : 0;
        for (int j=0;j<rem;j++){
            int s = __shfl_sync(0xffffffffu, sv, j);
            float4 vc = xc4[s*32+lane], vf = xf4[s*32+lane];
            ac.x+=vc.x; ac.y+=vc.y; ac.z+=vc.z; ac.w+=vc.w;
            af.x+=vf.x; af.y+=vf.y; af.z+=vf.z; af.w+=vf.w;
        }
    }
    float ri = g_rs_in[w];
    ac.x*=ri; ac.y*=ri; ac.z*=ri; ac.w*=ri;
    af.x*=ri; af.y*=ri; af.z*=ri; af.w*=ri;
    float4* agg4 = (float4*)g_agg;
    agg4[w*64 + lane]      = ac;   // cols 0..127
    agg4[w*64 + 32 + lane] = af;   // cols 128..255
}

// ---------------- tf32 mma.sync GEMM, templated epilogue ----------------
// EPI==0: C = (A@B) * rowscale[row]          (writes g_xf)
// EPI==1: C = relu(LN(A@B + bias)*gamma+beta) (final output)
template<int EPI>
__global__ void __launch_bounds__(256,1) gemm_kernel(
    const float* __restrict__ A, const float* __restrict__ B, float* __restrict__ C,
    int K, const float* __restrict__ rowscale, const float* __restrict__ bias,
    const float* __restrict__ gamma, const float* __restrict__ beta)
{
    extern __shared__ float smem[];
    float* As = smem;
    float* Bs = smem + 2*BM*AST;
    const int tid = threadIdx.x, lane = tid & 31, wid = tid >> 5;
    const int wm = wid & 3, wn = wid >> 2;           // 4x2 warp grid: 32x64 per warp
    const int g = lane >> 2, t = lane & 3;
    const long long brow = (long long)blockIdx.x * BM;

    float acc[2][8][4];
    #pragma unroll
    for (int i=0;i<2;i++)
        #pragma unroll
        for (int j=0;j<8;j++)
            #pragma unroll
            for (int l=0;l<4;l++) acc[i][j][l] = 0.f;

    const int KT = K / BK;

    auto load_tile = [&](int buf, int kt){
        const int k0 = kt * BK;
        float* as = As + buf*BM*AST;
        float* bs = Bs + buf*BK*BST;
        #pragma unroll
        for (int i=0;i<4;i++){
            int id = tid + i*256;
            int r = id >> 3, c = (id & 7) * 4;
            cp16(as + r*AST + c, A + (brow + r)*K + k0 + c);
        }
        #pragma unroll
        for (int i=0;i<4;i++){
            int id = tid + i*256;
            int r = id >> 5, c = (id & 31) * 4;
            cp16(bs + r*BST + c, B + (long long)(k0 + r)*BN + c);
        }
        asm volatile("cp.async.commit_group;\n");
    };

    load_tile(0, 0);
    for (int kt=0; kt<KT; kt++){
        int cur = kt & 1;
        if (kt + 1 < KT){
            load_tile(cur^1, kt+1);
            asm volatile("cp.async.wait_group 1;\n");
        } else {
            asm volatile("cp.async.wait_group 0;\n");
        }
        __syncthreads();
        const float* as = As + cur*BM*AST;
        const float* bs = Bs + cur*BK*BST;
        #pragma unroll
        for (int kk=0; kk<BK; kk+=8){
            uint32_t af[2][4];
            #pragma unroll
            for (int mt=0; mt<2; mt++){
                int r0 = wm*32 + mt*16 + g;
                af[mt][0] = f2tf(as[ r0     *AST + kk + t    ]);
                af[mt][1] = f2tf(as[(r0 + 8)*AST + kk + t    ]);
                af[mt][2] = f2tf(as[ r0     *AST + kk + t + 4]);
                af[mt][3] = f2tf(as[(r0 + 8)*AST + kk + t + 4]);
            }
            #pragma unroll
            for (int nt=0; nt<8; nt++){
                int c0 = wn*64 + nt*8 + g;
                uint32_t b0 = __float_as_uint(bs[(kk + t    )*BST + c0]);
                uint32_t b1 = __float_as_uint(bs[(kk + t + 4)*BST + c0]);
                mma8(acc[0][nt], af[0], b0, b1);
                mma8(acc[1][nt], af[1], b0, b1);
            }
        }
        __syncthreads();
    }

    if (EPI == 0){
        #pragma unroll
        for (int mt=0; mt<2; mt++){
            int r0 = (int)brow + wm*32 + mt*16 + g;
            float s0 = rowscale[r0], s1 = rowscale[r0+8];
            #pragma unroll
            for (int nt=0; nt<8; nt++){
                int c0 = wn*64 + nt*8 + 2*t;
                C[(long long) r0   *BN + c0    ] = acc[mt][nt][0]*s0;
                C[(long long) r0   *BN + c0 + 1] = acc[mt][nt][1]*s0;
                C[(long long)(r0+8)*BN + c0    ] = acc[mt][nt][2]*s1;
                C[(long long)(r0+8)*BN + c0 + 1] = acc[mt][nt][3]*s1;
            }
        }
    } else {
        // fused bias + LayerNorm + ReLU via smem staging (pitch 133 -> conflict-free rows)
        float* sm = smem;   // safe: main loop ended with __syncthreads()
        #pragma unroll
        for (int mt=0; mt<2; mt++){
            int r0 = wm*32 + mt*16 + g;
            #pragma unroll
            for (int nt=0; nt<8; nt++){
                int c0 = wn*64 + nt*8 + 2*t;
                sm[ r0   *EPI_PITCH + c0    ] = acc[mt][nt][0];
                sm[ r0   *EPI_PITCH + c0 + 1] = acc[mt][nt][1];
                sm[(r0+8)*EPI_PITCH + c0    ] = acc[mt][nt][2];
                sm[(r0+8)*EPI_PITCH + c0 + 1] = acc[mt][nt][3];
            }
        }
        __syncthreads();
        if (tid < 128){
            int r = tid;
            float s = 0.f, s2 = 0.f;
            #pragma unroll 8
            for (int c=0;c<128;c++){
                float v = sm[r*EPI_PITCH + c] + bias[c];
                s += v; s2 += v*v;
            }
            float mu   = s  * (1.f/128.f);
            float var  = s2 * (1.f/128.f) - mu*mu;
            float rstd = rsqrtf(var + 1e-5f);
            long long ro = (brow + r) * 128;
            #pragma unroll 8
            for (int c=0;c<128;c++){
                float v = sm[r*EPI_PITCH + c] + bias[c];
                float o = (v - mu)*rstd*gamma[c] + beta[c];
                C[ro + c] = fmaxf(o, 0.f);
            }
        }
    }
}

// ---------------- launcher ----------------
extern "C" void kernel_launch(void* const* d_in, const int* in_sizes, int n_in,
                              void* d_out, int out_size){
    const float* curr_h   = (const float*)d_in[0];
    const float* next_h   = (const float*)d_in[1];
    const float* curr_inc = (const float*)d_in[2];
    const float* Wc    = (const float*)d_in[3];
    const float* bc    = (const float*)d_in[4];
    const float* Wf    = (const float*)d_in[5];
    const float* bf    = (const float*)d_in[6];
    const float* cw    = (const float*)d_in[7];
    const float* tw    = (const float*)d_in[8];
    const float* gamma = (const float*)d_in[9];
    const float* beta  = (const float*)d_in[10];
    const int* esrc = (const int*)d_in[11];
    const int* edst = (const int*)d_in[12];
    float* out = (float*)d_out;

    void *p_nh, *p_xf, *p_agg, *p_wcat, *p_b2, *p_rso;
    cudaGetSymbolAddress(&p_nh,   g_nh_t);
    cudaGetSymbolAddress(&p_xf,   g_xf);
    cudaGetSymbolAddress(&p_agg,  g_agg);
    cudaGetSymbolAddress(&p_wcat, g_wcat);
    cudaGetSymbolAddress(&p_b2,   g_b2);
    cudaGetSymbolAddress(&p_rso,  g_rs_out);

    cudaFuncSetAttribute(gemm_kernel<0>, cudaFuncAttributeMaxDynamicSharedMemorySize, SMEM_BYTES);
    cudaFuncSetAttribute(gemm_kernel<1>, cudaFuncAttributeMaxDynamicSharedMemorySize, SMEM_BYTES);

    zero_kernel   <<<64,   256>>>();
    degree_kernel <<<2048, 256>>>(esrc, edst);
    scan_kernel   <<<1,   1024>>>();
    scatter_kernel<<<2048, 256>>>(esrc, edst);
    xc_kernel     <<<2048, 256>>>(curr_h);
    roundb_kernel <<<4096, 256>>>(next_h);
    prep_kernel   <<<128,  256>>>(Wc, bc, Wf, bf, cw, tw);

    // fused_in = inc @ nh, scaled by rsqrt(out_deg) -> g_xf
    gemm_kernel<0><<<128, 256, SMEM_BYTES>>>(curr_inc, (const float*)p_nh, (float*)p_xf,
                                             MM, (const float*)p_rso,
                                             nullptr, nullptr, nullptr);
    // graph aggregation for both paths -> g_agg [N, 256]
    spmm_kernel   <<<2048, 256>>>();
    // [N,256]@[256,128] + bias + LN + ReLU -> out
    gemm_kernel<1><<<128, 256, SMEM_BYTES>>>((const float*)p_agg, (const float*)p_wcat, out,
                                             2*DD, nullptr, (const float*)p_b2, gamma, beta);
}